// round 16
// baseline (speedup 1.0000x reference)
#include <cuda_runtime.h>
#include <cuda_bf16.h>
#include <cstdint>
#include <cstddef>

// Problem constants
#define NN    50000
#define EE    800000
#define FIN   128
#define HCDIM 292    // 4 heads * 73 ch
#define NCAT  584    // 2*HCDIM (merged xl|xr GEMM)
#define S1    128    // layer-1 section width (hi|lo)
#define S2    320    // layer-2 section width (292 padded to 320)
#define HALFR 25088  // 196 * 128 rows (gemm2 pipeline split)

// ---------------- static scratch ----------------
__device__ float g_xl [(size_t)NN * HCDIM];
__device__ float g_xr [(size_t)NN * HCDIM];
__device__ float g_agg[(size_t)NN * HCDIM];
__device__ float g_sums[2 * HCDIM];
__device__ __nv_bfloat16 g_Abig[(size_t)NN * (2 * S2)];                  // [hi|lo] A
__device__ __nv_bfloat16 g_Bcat[(size_t)NCAT * (2 * S1 + 2 * S2)];       // B1 then B2
// CSR by destination
__device__ int g_deg [NN];
__device__ int g_off [NN + 1];
__device__ int g_cur [NN];
__device__ int g_srcs[EE];

// ---------------- PTX helpers ----------------
__device__ __forceinline__ uint32_t smem_u32(const void* p) {
    uint32_t a;
    asm("{ .reg .u64 t; cvta.to.shared.u64 t, %1; cvt.u32.u64 %0, t; }" : "=r"(a) : "l"(p));
    return a;
}
__device__ __forceinline__ void cp_async16(uint32_t dst, const void* src, int sz) {
    asm volatile("cp.async.cg.shared.global [%0], [%1], 16, %2;"
                 :: "r"(dst), "l"(src), "r"(sz) : "memory");
}
__device__ __forceinline__ void cp_commit() {
    asm volatile("cp.async.commit_group;" ::: "memory");
}
template <int N>
__device__ __forceinline__ void cp_wait() {
    asm volatile("cp.async.wait_group %0;" :: "n"(N) : "memory");
}
__device__ __forceinline__ void ldm_x4(uint32_t* r, uint32_t addr) {
    asm volatile("ldmatrix.sync.aligned.m8n8.x4.shared.b16 {%0,%1,%2,%3}, [%4];"
                 : "=r"(r[0]), "=r"(r[1]), "=r"(r[2]), "=r"(r[3]) : "r"(addr));
}
__device__ __forceinline__ void mma_bf16(float* c, const uint32_t* a, const uint32_t* b) {
    asm volatile("mma.sync.aligned.m16n8k16.row.col.f32.bf16.bf16.f32 "
                 "{%0,%1,%2,%3}, {%4,%5,%6,%7}, {%8,%9}, {%0,%1,%2,%3};"
                 : "+f"(c[0]), "+f"(c[1]), "+f"(c[2]), "+f"(c[3])
                 : "r"(a[0]), "r"(a[1]), "r"(a[2]), "r"(a[3]), "r"(b[0]), "r"(b[1]));
}

__device__ __forceinline__ float hsel(int j, float h0, float h1, float h2, float h3) {
    return (j < 73) ? h0 : (j < 146) ? h1 : (j < 219) ? h2 : h3;
}

// ---------------- zero kernels ----------------
__global__ void zero_deg_sums() {
    int i = blockIdx.x * blockDim.x + threadIdx.x;
    if (i < NN) g_deg[i] = 0;
    if (i < 2 * HCDIM) g_sums[i] = 0.0f;
}
__global__ void zero_sums() {
    int i = blockIdx.x * blockDim.x + threadIdx.x;
    if (i < 2 * HCDIM) g_sums[i] = 0.0f;
}

// ---------------- CSR build ----------------
__global__ void csr_count(const int* __restrict__ ei) {
    int e = blockIdx.x * blockDim.x + threadIdx.x;
    if (e < EE) atomicAdd(&g_deg[ei[EE + e]], 1);
}
__global__ __launch_bounds__(1024) void csr_scan() {
    __shared__ int ssum[1024];
    const int CHUNK = (NN + 1023) / 1024;
    int t = threadIdx.x;
    int begin = t * CHUNK;
    int end = begin + CHUNK; if (end > NN) end = NN;
    int local = 0;
    for (int i = begin; i < end && i < NN; i++) local += g_deg[i];
    ssum[t] = local;
    __syncthreads();
    for (int o = 1; o < 1024; o <<= 1) {
        int v = (t >= o) ? ssum[t - o] : 0;
        __syncthreads();
        ssum[t] += v;
        __syncthreads();
    }
    int run = (t > 0) ? ssum[t - 1] : 0;
    for (int i = begin; i < end && i < NN; i++) {
        g_off[i] = run; g_cur[i] = run; run += g_deg[i];
    }
    if (t == 1023) g_off[NN] = ssum[1023];
}
__global__ void csr_scatter(const int* __restrict__ ei) {
    int e = blockIdx.x * blockDim.x + threadIdx.x;
    if (e < EE) {
        int dst = ei[EE + e];
        int pos = atomicAdd(&g_cur[dst], 1);
        g_srcs[pos] = ei[e];
    }
}

// ---------------- hi|lo split conversion ----------------
// out row layout: [hi(K), pad0.., | lo(K), pad0..], row width 2*S.
__global__ void convert_hilo(const float* __restrict__ X, __nv_bfloat16* __restrict__ out,
                             int M, int K, int S)
{
    int Kp = 2 * S;
    size_t total = (size_t)M * Kp;
    size_t stride = (size_t)gridDim.x * blockDim.x;
    for (size_t i = (size_t)blockIdx.x * blockDim.x + threadIdx.x; i < total; i += stride) {
        int row = (int)(i / Kp);
        int kk  = (int)(i - (size_t)row * Kp);
        int sec = (kk >= S) ? 1 : 0;
        int k   = kk - sec * S;
        __nv_bfloat16 o;
        if (k < K) {
            float x = X[(size_t)row * K + k];
            __nv_bfloat16 h = __float2bfloat16_rn(x);
            o = sec ? __float2bfloat16_rn(x - __bfloat162float(h)) : h;
        } else {
            o = __float2bfloat16_rn(0.0f);
        }
        out[i] = o;
    }
}

// ---------------- warp-MMA bf16 GEMM: 3-segment split-precision ----------------
// C = Ahi*Bhi^T + Ahi*Blo^T + Alo*Bhi^T over sections of width S ([hi|lo] layout).
#define PADW  40
#define ROWB  (PADW * 2)
#define ABUF  (128 * ROWB)
#define BBUF  (128 * ROWB)

__global__ __launch_bounds__(256) void gemm_mma(
    const __nv_bfloat16* __restrict__ Ag, const __nv_bfloat16* __restrict__ Bg,
    const float* __restrict__ bl, const float* __restrict__ br,
    int M, int S, int mBase)
{
    __shared__ alignas(128) char smem[2 * ABUF + 2 * BBUF];
    uint32_t sb = smem_u32(smem);
    int tid  = threadIdx.x;
    int wid  = tid >> 5;
    int lane = tid & 31;
    int wm   = wid >> 1;
    int wn   = wid & 1;
    int bm = mBase + blockIdx.y * 128;
    int bn = blockIdx.x * 128;

    int Kp  = 2 * S;
    int per = S >> 5;          // chunks per segment
    int nc  = 3 * per;

    float acc[2][8][4];
#pragma unroll
    for (int i = 0; i < 2; i++)
#pragma unroll
        for (int j = 0; j < 8; j++)
#pragma unroll
            for (int t = 0; t < 4; t++) acc[i][j][t] = 0.0f;

    auto load_chunk = [&](int g, int buf) {
        int seg = g / per, cc = g - seg * per;
        int ae = ((seg == 2) ? S : 0) + cc * 32;
        int be = ((seg == 1) ? S : 0) + cc * 32;
        uint32_t sA = sb + buf * ABUF;
        uint32_t sBm = sb + 2 * ABUF + buf * BBUF;
#pragma unroll
        for (int t = tid; t < 512; t += 256) {
            int row = t >> 2, segm = t & 3;
            int grow = bm + row;
            cp_async16(sA + row * ROWB + segm * 16,
                       Ag + (size_t)grow * Kp + ae + segm * 8,
                       (grow < M) ? 16 : 0);
        }
#pragma unroll
        for (int t = tid; t < 512; t += 256) {
            int row = t >> 2, segm = t & 3;
            int grow = bn + row;
            cp_async16(sBm + row * ROWB + segm * 16,
                       Bg + (size_t)grow * Kp + be + segm * 8,
                       (grow < NCAT) ? 16 : 0);
        }
    };

    load_chunk(0, 0);
    cp_commit();

    uint32_t aoff = (uint32_t)((wm * 32 + (lane & 15)) * ROWB + ((lane >> 4) * 16));
    uint32_t boff = (uint32_t)((wn * 64 + (lane & 7) + ((lane >> 4) << 3)) * ROWB
                               + (((lane >> 3) & 1) * 16));

    for (int c = 0; c < nc; c++) {
        int buf = c & 1;
        if (c + 1 < nc) { load_chunk(c + 1, buf ^ 1); cp_commit(); cp_wait<1>(); }
        else            { cp_wait<0>(); }
        __syncthreads();

        uint32_t sA = sb + buf * ABUF + aoff;
        uint32_t sBm = sb + 2 * ABUF + buf * BBUF + boff;
#pragma unroll
        for (int s = 0; s < 2; s++) {
            uint32_t a[2][4], b[4][4];
            ldm_x4(a[0], sA + s * 32);
            ldm_x4(a[1], sA + s * 32 + 16 * ROWB);
            ldm_x4(b[0], sBm + s * 32);
            ldm_x4(b[1], sBm + s * 32 + 16 * ROWB);
            ldm_x4(b[2], sBm + s * 32 + 32 * ROWB);
            ldm_x4(b[3], sBm + s * 32 + 48 * ROWB);
#pragma unroll
            for (int mt = 0; mt < 2; mt++)
#pragma unroll
                for (int nt = 0; nt < 8; nt++)
                    mma_bf16(acc[mt][nt], a[mt], &b[nt >> 1][(nt & 1) * 2]);
        }
        __syncthreads();
    }

    int r0 = lane >> 2;
    int c0 = (lane & 3) * 2;
#pragma unroll
    for (int mt = 0; mt < 2; mt++) {
#pragma unroll
        for (int nt = 0; nt < 8; nt++) {
            int col = bn + wn * 64 + nt * 8 + c0;
            if (col >= NCAT) continue;
            bool isl = (col < HCDIM);
            int cc = isl ? col : col - HCDIM;
            float* dst = isl ? g_xl : g_xr;
            const float* bias = isl ? bl : br;
            float b0 = bias[cc], b1 = bias[cc + 1];
            int row = bm + wm * 32 + mt * 16 + r0;
            if (row < M) {
                float2 v = make_float2(acc[mt][nt][0] + b0, acc[mt][nt][1] + b1);
                *(float2*)(dst + (size_t)row * HCDIM + cc) = v;
            }
            if (row + 8 < M) {
                float2 v = make_float2(acc[mt][nt][2] + b0, acc[mt][nt][3] + b1);
                *(float2*)(dst + (size_t)(row + 8) * HCDIM + cc) = v;
            }
        }
    }
}

// ---------------- CSR edge pass + fused BN statistics ----------------
__global__ __launch_bounds__(256) void edge_csr(const float* __restrict__ att)
{
    __shared__ float satt[HCDIM];
    __shared__ float sred[256 * 20];
    for (int i = threadIdx.x; i < HCDIM; i += 256) satt[i] = att[i];
    __syncthreads();

    int gt  = blockIdx.x * 256 + threadIdx.x;
    int n   = gt >> 4;
    int sub = gt & 15;
    const unsigned gmask = 0xFFFFu << (threadIdx.x & 16);  // group-local mask (UB otherwise)

    const float4* pr = (const float4*)(g_xr + (size_t)n * HCDIM);
    const float4* pw = (const float4*)satt;
    float4 xr[5], acc[5];
#pragma unroll
    for (int t = 0; t < 5; t++) {
        int i = sub + 16 * t;
        acc[t] = make_float4(0.f, 0.f, 0.f, 0.f);
        if (i < 73) xr[t] = __ldcs(pr + i);
    }
    float d0 = 0.f, d1 = 0.f, d2 = 0.f, d3 = 0.f;

    int k0 = g_off[n], k1 = g_off[n + 1];
    int k = k0;
    for (; k + 1 < k1; k += 2) {
        int srcA = g_srcs[k];
        int srcB = g_srcs[k + 1];
        const float4* pA = (const float4*)(g_xl + (size_t)srcA * HCDIM);
        const float4* pB = (const float4*)(g_xl + (size_t)srcB * HCDIM);
        float4 a[5], b[5];
#pragma unroll
        for (int t = 0; t < 5; t++) {
            int i = sub + 16 * t;
            if (i < 73) { a[t] = pA[i]; b[t] = pB[i]; }
        }
        float u0 = 0.f, u1 = 0.f, u2 = 0.f, u3 = 0.f;
        float v0 = 0.f, v1 = 0.f, v2 = 0.f, v3 = 0.f;
#pragma unroll
        for (int t = 0; t < 5; t++) {
            int i = sub + 16 * t;
            if (i < 73) {
                float4 w = pw[i];
                int j = 4 * i;
                float f, p;
                f = a[t].x + xr[t].x; f = fmaxf(f, 0.f) + 0.2f * fminf(f, 0.f); p = f * w.x;
                if (j + 0 < 73) u0 += p; else if (j + 0 < 146) u1 += p; else if (j + 0 < 219) u2 += p; else u3 += p;
                f = a[t].y + xr[t].y; f = fmaxf(f, 0.f) + 0.2f * fminf(f, 0.f); p = f * w.y;
                if (j + 1 < 73) u0 += p; else if (j + 1 < 146) u1 += p; else if (j + 1 < 219) u2 += p; else u3 += p;
                f = a[t].z + xr[t].z; f = fmaxf(f, 0.f) + 0.2f * fminf(f, 0.f); p = f * w.z;
                if (j + 2 < 73) u0 += p; else if (j + 2 < 146) u1 += p; else if (j + 2 < 219) u2 += p; else u3 += p;
                f = a[t].w + xr[t].w; f = fmaxf(f, 0.f) + 0.2f * fminf(f, 0.f); p = f * w.w;
                if (j + 3 < 73) u0 += p; else if (j + 3 < 146) u1 += p; else if (j + 3 < 219) u2 += p; else u3 += p;

                f = b[t].x + xr[t].x; f = fmaxf(f, 0.f) + 0.2f * fminf(f, 0.f); p = f * w.x;
                if (j + 0 < 73) v0 += p; else if (j + 0 < 146) v1 += p; else if (j + 0 < 219) v2 += p; else v3 += p;
                f = b[t].y + xr[t].y; f = fmaxf(f, 0.f) + 0.2f * fminf(f, 0.f); p = f * w.y;
                if (j + 1 < 73) v0 += p; else if (j + 1 < 146) v1 += p; else if (j + 1 < 219) v2 += p; else v3 += p;
                f = b[t].z + xr[t].z; f = fmaxf(f, 0.f) + 0.2f * fminf(f, 0.f); p = f * w.z;
                if (j + 2 < 73) v0 += p; else if (j + 2 < 146) v1 += p; else if (j + 2 < 219) v2 += p; else v3 += p;
                f = b[t].w + xr[t].w; f = fmaxf(f, 0.f) + 0.2f * fminf(f, 0.f); p = f * w.w;
                if (j + 3 < 73) v0 += p; else if (j + 3 < 146) v1 += p; else if (j + 3 < 219) v2 += p; else v3 += p;
            }
        }
#pragma unroll
        for (int o = 8; o > 0; o >>= 1) {
            u0 += __shfl_xor_sync(gmask, u0, o, 16);
            v0 += __shfl_xor_sync(gmask, v0, o, 16);
            u1 += __shfl_xor_sync(gmask, u1, o, 16);
            v1 += __shfl_xor_sync(gmask, v1, o, 16);
            u2 += __shfl_xor_sync(gmask, u2, o, 16);
            v2 += __shfl_xor_sync(gmask, v2, o, 16);
            u3 += __shfl_xor_sync(gmask, u3, o, 16);
            v3 += __shfl_xor_sync(gmask, v3, o, 16);
        }
        float eA0 = expf(u0), eA1 = expf(u1), eA2 = expf(u2), eA3 = expf(u3);
        float eB0 = expf(v0), eB1 = expf(v1), eB2 = expf(v2), eB3 = expf(v3);
        d0 += eA0 + eB0; d1 += eA1 + eB1; d2 += eA2 + eB2; d3 += eA3 + eB3;
#pragma unroll
        for (int t = 0; t < 5; t++) {
            int i = sub + 16 * t;
            if (i < 73) {
                int j = 4 * i;
                float mA0 = hsel(j + 0, eA0, eA1, eA2, eA3), mB0 = hsel(j + 0, eB0, eB1, eB2, eB3);
                float mA1 = hsel(j + 1, eA0, eA1, eA2, eA3), mB1 = hsel(j + 1, eB0, eB1, eB2, eB3);
                float mA2 = hsel(j + 2, eA0, eA1, eA2, eA3), mB2 = hsel(j + 2, eB0, eB1, eB2, eB3);
                float mA3 = hsel(j + 3, eA0, eA1, eA2, eA3), mB3 = hsel(j + 3, eB0, eB1, eB2, eB3);
                acc[t].x += a[t].x * mA0 + b[t].x * mB0;
                acc[t].y += a[t].y * mA1 + b[t].y * mB1;
                acc[t].z += a[t].z * mA2 + b[t].z * mB2;
                acc[t].w += a[t].w * mA3 + b[t].w * mB3;
            }
        }
    }
    for (; k < k1; k++) {
        int src = g_srcs[k];
        const float4* pl = (const float4*)(g_xl + (size_t)src * HCDIM);
        float4 a[5];
        float s0 = 0.f, s1 = 0.f, s2 = 0.f, s3 = 0.f;
#pragma unroll
        for (int t = 0; t < 5; t++) {
            int i = sub + 16 * t;
            if (i < 73) {
                float4 av = pl[i];
                a[t] = av;
                float4 w = pw[i];
                int j = 4 * i;
                float f, p;
                f = av.x + xr[t].x; f = fmaxf(f, 0.f) + 0.2f * fminf(f, 0.f); p = f * w.x;
                if (j + 0 < 73) s0 += p; else if (j + 0 < 146) s1 += p; else if (j + 0 < 219) s2 += p; else s3 += p;
                f = av.y + xr[t].y; f = fmaxf(f, 0.f) + 0.2f * fminf(f, 0.f); p = f * w.y;
                if (j + 1 < 73) s0 += p; else if (j + 1 < 146) s1 += p; else if (j + 1 < 219) s2 += p; else s3 += p;
                f = av.z + xr[t].z; f = fmaxf(f, 0.f) + 0.2f * fminf(f, 0.f); p = f * w.z;
                if (j + 2 < 73) s0 += p; else if (j + 2 < 146) s1 += p; else if (j + 2 < 219) s2 += p; else s3 += p;
                f = av.w + xr[t].w; f = fmaxf(f, 0.f) + 0.2f * fminf(f, 0.f); p = f * w.w;
                if (j + 3 < 73) s0 += p; else if (j + 3 < 146) s1 += p; else if (j + 3 < 219) s2 += p; else s3 += p;
            }
        }
#pragma unroll
        for (int o = 8; o > 0; o >>= 1) {
            s0 += __shfl_xor_sync(gmask, s0, o, 16);
            s1 += __shfl_xor_sync(gmask, s1, o, 16);
            s2 += __shfl_xor_sync(gmask, s2, o, 16);
            s3 += __shfl_xor_sync(gmask, s3, o, 16);
        }
        float e0 = expf(s0), e1 = expf(s1), e2 = expf(s2), e3 = expf(s3);
        d0 += e0; d1 += e1; d2 += e2; d3 += e3;
#pragma unroll
        for (int t = 0; t < 5; t++) {
            int i = sub + 16 * t;
            if (i < 73) {
                int j = 4 * i;
                acc[t].x += a[t].x * hsel(j + 0, e0, e1, e2, e3);
                acc[t].y += a[t].y * hsel(j + 1, e0, e1, e2, e3);
                acc[t].z += a[t].z * hsel(j + 2, e0, e1, e2, e3);
                acc[t].w += a[t].w * hsel(j + 3, e0, e1, e2, e3);
            }
        }
    }

    float i0 = 1.0f / (d0 + 1e-16f);
    float i1 = 1.0f / (d1 + 1e-16f);
    float i2 = 1.0f / (d2 + 1e-16f);
    float i3 = 1.0f / (d3 + 1e-16f);
    float4* po = (float4*)(g_agg + (size_t)n * HCDIM);
    float* myred = sred + threadIdx.x * 20;
#pragma unroll
    for (int t = 0; t < 5; t++) {
        int i = sub + 16 * t;
        if (i < 73) {
            int j = 4 * i;
            float4 o = make_float4(acc[t].x * hsel(j + 0, i0, i1, i2, i3),
                                   acc[t].y * hsel(j + 1, i0, i1, i2, i3),
                                   acc[t].z * hsel(j + 2, i0, i1, i2, i3),
                                   acc[t].w * hsel(j + 3, i0, i1, i2, i3));
            __stcs(po + i, o);
            myred[t * 4 + 0] = o.x;
            myred[t * 4 + 1] = o.y;
            myred[t * 4 + 2] = o.z;
            myred[t * 4 + 3] = o.w;
        } else {
            myred[t * 4 + 0] = 0.f;
            myred[t * 4 + 1] = 0.f;
            myred[t * 4 + 2] = 0.f;
            myred[t * 4 + 3] = 0.f;
        }
    }
    __syncthreads();

    for (int c = threadIdx.x; c < HCDIM; c += 256) {
        int chunk = c >> 2;
        int lanec = chunk & 15;
        int slot  = (chunk >> 4) * 4 + (c & 3);
        float s = 0.f, q = 0.f;
#pragma unroll
        for (int g = 0; g < 16; g++) {
            float v = sred[(g * 16 + lanec) * 20 + slot];
            s += v;
            q += v * v;
        }
        atomicAdd(&g_sums[c], s);
        atomicAdd(&g_sums[HCDIM + c], q);
    }
}

// ---------------- BN apply + leaky relu + hi|lo A conversion (row-ranged) ----------------
__global__ __launch_bounds__(256) void bn_apply_convert(
    const float* __restrict__ X, __nv_bfloat16* __restrict__ out,
    const float* __restrict__ gamma, const float* __restrict__ beta,
    int rowBase, int nRows)
{
    size_t idx = (size_t)blockIdx.x * blockDim.x + threadIdx.x;
    size_t total = (size_t)nRows * HCDIM;
    if (idx >= total) return;
    int row = rowBase + (int)(idx / HCDIM);
    int c   = (int)(idx % HCDIM);
    const float invN = 1.0f / (float)NN;
    float mu  = g_sums[c] * invN;
    float var = g_sums[HCDIM + c] * invN - mu * mu;
    float sc  = gamma[c] * rsqrtf(var + 1e-5f);
    float v   = (X[(size_t)row * HCDIM + c] - mu) * sc + beta[c];
    v = (v > 0.0f) ? v : 0.01f * v;
    __nv_bfloat16 h = __float2bfloat16_rn(v);
    __nv_bfloat16 l = __float2bfloat16_rn(v - __bfloat162float(h));
    size_t base = (size_t)row * (2 * S2);
    out[base + c]      = h;
    out[base + S2 + c] = l;
    if (c < S2 - HCDIM) {   // zero pads [292,320) in both sections (buffer reused across layers)
        out[base + HCDIM + c]      = __float2bfloat16_rn(0.0f);
        out[base + S2 + HCDIM + c] = __float2bfloat16_rn(0.0f);
    }
}

// ---------------- fused BN + leaky relu + classifier (layer 2) ----------------
__global__ __launch_bounds__(256) void bn_apply_classify(
    const float* __restrict__ X,
    const float* __restrict__ gamma, const float* __restrict__ beta,
    const float* __restrict__ Wc, const float* __restrict__ bc,
    float* __restrict__ out)
{
    int gt   = blockIdx.x * 256 + threadIdx.x;
    int n    = gt >> 5;
    int lane = gt & 31;
    if (n >= NN) return;
    const float invN = 1.0f / (float)NN;
    const float* row = X + (size_t)n * HCDIM;
    float a0 = 0.f, a1 = 0.f;
    for (int c = lane; c < HCDIM; c += 32) {
        float mu  = g_sums[c] * invN;
        float var = g_sums[HCDIM + c] * invN - mu * mu;
        float sc  = gamma[c] * rsqrtf(var + 1e-5f);
        float v   = (row[c] - mu) * sc + beta[c];
        v = (v > 0.0f) ? v : 0.01f * v;
        a0 += v * Wc[c];
        a1 += v * Wc[HCDIM + c];
    }
#pragma unroll
    for (int o = 16; o > 0; o >>= 1) {
        a0 += __shfl_down_sync(0xffffffffu, a0, o);
        a1 += __shfl_down_sync(0xffffffffu, a1, o);
    }
    if (lane == 0) {
        out[(size_t)n * 2 + 0] = a0 + bc[0];
        out[(size_t)n * 2 + 1] = a1 + bc[1];
    }
}

// ---------------- launcher ----------------
extern "C" void kernel_launch(void* const* d_in, const int* in_sizes, int n_in,
                              void* d_out, int out_size)
{
    const float* x     = (const float*)d_in[0];
    const int*   ei    = (const int*)d_in[1];
    const float* Wl1   = (const float*)d_in[2];
    const float* bl1   = (const float*)d_in[3];
    const float* Wr1   = (const float*)d_in[4];
    const float* br1   = (const float*)d_in[5];
    const float* att1  = (const float*)d_in[6];
    const float* Wl2   = (const float*)d_in[8];
    const float* bl2   = (const float*)d_in[9];
    const float* Wr2   = (const float*)d_in[10];
    const float* br2   = (const float*)d_in[11];
    const float* att2  = (const float*)d_in[12];
    const float* gamma = (const float*)d_in[14];
    const float* beta  = (const float*)d_in[15];
    const float* Wc    = (const float*)d_in[16];
    const float* bc    = (const float*)d_in[17];
    float*       out   = (float*)d_out;

    float* agg; cudaGetSymbolAddress((void**)&agg, g_agg);
    __nv_bfloat16* Abig; cudaGetSymbolAddress((void**)&Abig, g_Abig);
    __nv_bfloat16* Bcat; cudaGetSymbolAddress((void**)&Bcat, g_Bcat);
    __nv_bfloat16* B1 = Bcat;                                    // NCAT rows, width 2*S1
    __nv_bfloat16* B2 = Bcat + (size_t)NCAT * (2 * S1);          // NCAT rows, width 2*S2

    static cudaStream_t s2s = nullptr;
    static cudaEvent_t evFork = nullptr, evJoin = nullptr, evC = nullptr, evG = nullptr;
    if (!s2s) {
        cudaStreamCreateWithFlags(&s2s, cudaStreamNonBlocking);
        cudaEventCreateWithFlags(&evFork, cudaEventDisableTiming);
        cudaEventCreateWithFlags(&evJoin, cudaEventDisableTiming);
        cudaEventCreateWithFlags(&evC, cudaEventDisableTiming);
        cudaEventCreateWithFlags(&evG, cudaEventDisableTiming);
    }

    dim3 gemm_grid1((NCAT + 127) / 128, (NN + 127) / 128);       // (5, 391)
    dim3 gemm_grid2a((NCAT + 127) / 128, HALFR / 128);           // (5, 196)
    dim3 gemm_grid2b((NCAT + 127) / 128, (NN - HALFR + 127) / 128); // (5, 195)
    int e_blocks    = (EE + 255) / 256;
    int edge_blocks = (NN * 16 + 255) / 256;
    int cls_blocks  = (NN * 32 + 255) / 256;
    int convA1_blocks = (int)(((size_t)NN * 2 * S1 + 255) / 256);
    int convB1_blocks = (HCDIM * 2 * S1 + 255) / 256;
    int convB2_blocks = (HCDIM * 2 * S2 + 255) / 256;
    int bnc0_blocks = (int)(((size_t)HALFR * HCDIM + 255) / 256);
    int bnc1_blocks = (int)(((size_t)(NN - HALFR) * HCDIM + 255) / 256);

    // ---- fork: chain B (CSR build + layer-2 weight conversions) on s2s ----
    cudaEventRecord(evFork, 0);
    cudaStreamWaitEvent(s2s, evFork, 0);
    zero_deg_sums<<<(NN + 255) / 256, 256, 0, s2s>>>();
    csr_count   <<<e_blocks, 256, 0, s2s>>>(ei);
    csr_scan    <<<1, 1024, 0, s2s>>>();
    csr_scatter <<<e_blocks, 256, 0, s2s>>>(ei);
    convert_hilo<<<convB2_blocks, 256, 0, s2s>>>(Wl2, B2,                        HCDIM, HCDIM, S2);
    convert_hilo<<<convB2_blocks, 256, 0, s2s>>>(Wr2, B2 + (size_t)HCDIM*(2*S2), HCDIM, HCDIM, S2);
    cudaEventRecord(evJoin, s2s);

    // ---- chain A: layer-1 GEMM inputs + GEMM (default stream) ----
    convert_hilo<<<convB1_blocks, 256>>>(Wl1, B1,                        HCDIM, FIN, S1);
    convert_hilo<<<convB1_blocks, 256>>>(Wr1, B1 + (size_t)HCDIM*(2*S1), HCDIM, FIN, S1);
    convert_hilo<<<convA1_blocks, 256>>>(x,   Abig, NN, FIN, S1);
    gemm_mma<<<gemm_grid1, 256>>>(Abig, B1, bl1, br1, NN, S1, 0);

    // ---- join: edge_csr needs gemm1 + CSR + zeroed sums ----
    cudaStreamWaitEvent(0, evJoin, 0);

    // ---------- layer 1 (BN stats fused into edge_csr) ----------
    edge_csr<<<edge_blocks, 256>>>(att1);

    // pipelined BN-convert / gemm2
    bn_apply_convert<<<bnc0_blocks, 256>>>(agg, Abig, gamma, beta, 0, HALFR);
    cudaEventRecord(evC, 0);
    bn_apply_convert<<<bnc1_blocks, 256>>>(agg, Abig, gamma, beta, HALFR, NN - HALFR);
    zero_sums<<<3, 256>>>();
    cudaStreamWaitEvent(s2s, evC, 0);
    gemm_mma<<<gemm_grid2a, 256, 0, s2s>>>(Abig, B2, bl2, br2, NN, S2, 0);
    cudaEventRecord(evG, s2s);
    gemm_mma<<<gemm_grid2b, 256>>>(Abig, B2, bl2, br2, NN, S2, HALFR);
    cudaStreamWaitEvent(0, evG, 0);

    // ---------- layer 2 ----------
    edge_csr<<<edge_blocks, 256>>>(att2);
    bn_apply_classify<<<cls_blocks, 256>>>(agg, gamma, beta, Wc, bc, out);

    (void)in_sizes; (void)n_in; (void)out_size;
}

// round 17
// speedup vs baseline: 1.0327x; 1.0327x over previous
#include <cuda_runtime.h>
#include <cuda_bf16.h>
#include <cstdint>
#include <cstddef>

// Problem constants
#define NN    50000
#define EE    800000
#define FIN   128
#define HCDIM 292    // 4 heads * 73 ch
#define NCAT  584    // 2*HCDIM (merged xl|xr GEMM)
#define KP1   384    // 3*128, layer-1 split-K
#define KP2   896    // 3*292=876 padded to 64-multiple
#define HALFR 25088  // 196 * 128 rows (gemm2 pipeline split)

// ---------------- static scratch ----------------
__device__ float g_xl [(size_t)NN * HCDIM];
__device__ float g_xr [(size_t)NN * HCDIM];
__device__ float g_agg[(size_t)NN * HCDIM];
__device__ float g_sums[2 * HCDIM];
__device__ __nv_bfloat16 g_Abig[(size_t)NN * KP2];        // split-precision A
__device__ __nv_bfloat16 g_Bcat[2][(size_t)NCAT * KP2];   // [Wl;Wr] per layer
// CSR by destination
__device__ int g_deg [NN];
__device__ int g_off [NN + 1];
__device__ int g_cur [NN];
__device__ int g_srcs[EE];

// ---------------- PTX helpers (baseline sm_80+ features only) ----------------
__device__ __forceinline__ uint32_t smem_u32(const void* p) {
    uint32_t a;
    asm("{ .reg .u64 t; cvta.to.shared.u64 t, %1; cvt.u32.u64 %0, t; }" : "=r"(a) : "l"(p));
    return a;
}
__device__ __forceinline__ void cp_async16(uint32_t dst, const void* src, int sz) {
    asm volatile("cp.async.cg.shared.global [%0], [%1], 16, %2;"
                 :: "r"(dst), "l"(src), "r"(sz) : "memory");
}
__device__ __forceinline__ void cp_commit() {
    asm volatile("cp.async.commit_group;" ::: "memory");
}
template <int N>
__device__ __forceinline__ void cp_wait() {
    asm volatile("cp.async.wait_group %0;" :: "n"(N) : "memory");
}
__device__ __forceinline__ void ldm_x4(uint32_t* r, uint32_t addr) {
    asm volatile("ldmatrix.sync.aligned.m8n8.x4.shared.b16 {%0,%1,%2,%3}, [%4];"
                 : "=r"(r[0]), "=r"(r[1]), "=r"(r[2]), "=r"(r[3]) : "r"(addr));
}
__device__ __forceinline__ void mma_bf16(float* c, const uint32_t* a, const uint32_t* b) {
    asm volatile("mma.sync.aligned.m16n8k16.row.col.f32.bf16.bf16.f32 "
                 "{%0,%1,%2,%3}, {%4,%5,%6,%7}, {%8,%9}, {%0,%1,%2,%3};"
                 : "+f"(c[0]), "+f"(c[1]), "+f"(c[2]), "+f"(c[3])
                 : "r"(a[0]), "r"(a[1]), "r"(a[2]), "r"(a[3]), "r"(b[0]), "r"(b[1]));
}

// head multiplier select (boundaries 73/146/219)
__device__ __forceinline__ float hsel(int j, float h0, float h1, float h2, float h3) {
    return (j < 73) ? h0 : (j < 146) ? h1 : (j < 219) ? h2 : h3;
}

// ---------------- zero kernels ----------------
__global__ void zero_deg_sums() {
    int i = blockIdx.x * blockDim.x + threadIdx.x;
    if (i < NN) g_deg[i] = 0;
    if (i < 2 * HCDIM) g_sums[i] = 0.0f;
}
__global__ void zero_sums() {
    int i = blockIdx.x * blockDim.x + threadIdx.x;
    if (i < 2 * HCDIM) g_sums[i] = 0.0f;
}

// ---------------- CSR build ----------------
__global__ void csr_count(const int* __restrict__ ei) {
    int e = blockIdx.x * blockDim.x + threadIdx.x;
    if (e < EE) atomicAdd(&g_deg[ei[EE + e]], 1);
}
__global__ __launch_bounds__(1024) void csr_scan() {
    __shared__ int ssum[1024];
    const int CHUNK = (NN + 1023) / 1024;
    int t = threadIdx.x;
    int begin = t * CHUNK;
    int end = begin + CHUNK; if (end > NN) end = NN;
    int local = 0;
    for (int i = begin; i < end && i < NN; i++) local += g_deg[i];
    ssum[t] = local;
    __syncthreads();
    for (int o = 1; o < 1024; o <<= 1) {
        int v = (t >= o) ? ssum[t - o] : 0;
        __syncthreads();
        ssum[t] += v;
        __syncthreads();
    }
    int run = (t > 0) ? ssum[t - 1] : 0;
    for (int i = begin; i < end && i < NN; i++) {
        g_off[i] = run; g_cur[i] = run; run += g_deg[i];
    }
    if (t == 1023) g_off[NN] = ssum[1023];
}
__global__ void csr_scatter(const int* __restrict__ ei) {
    int e = blockIdx.x * blockDim.x + threadIdx.x;
    if (e < EE) {
        int dst = ei[EE + e];
        int pos = atomicAdd(&g_cur[dst], 1);
        g_srcs[pos] = ei[e];
    }
}

// ---------------- split-precision conversions ----------------
// mode 0 (A): sections [hi, hi, lo]; mode 1 (B): [hi, lo, hi]; pad zeros.
__global__ void convert_split3(const float* __restrict__ X, __nv_bfloat16* __restrict__ out,
                               int M, int K, int Kp, int mode)
{
    size_t total = (size_t)M * Kp;
    size_t stride = (size_t)gridDim.x * blockDim.x;
    for (size_t i = (size_t)blockIdx.x * blockDim.x + threadIdx.x; i < total; i += stride) {
        int row = (int)(i / Kp);
        int kk  = (int)(i - (size_t)row * Kp);
        __nv_bfloat16 o;
        if (kk < 3 * K) {
            int sec = (kk < K) ? 0 : ((kk < 2 * K) ? 1 : 2);
            float x = X[(size_t)row * K + (kk - sec * K)];
            __nv_bfloat16 h = __float2bfloat16_rn(x);
            bool want_lo = (mode == 0) ? (sec == 2) : (sec == 1);
            o = want_lo ? __float2bfloat16_rn(x - __bfloat162float(h)) : h;
        } else {
            o = __float2bfloat16_rn(0.0f);
        }
        out[i] = o;
    }
}

// ---------------- warp-MMA bf16 GEMM (merged xl|xr, 128x128 CTA tile) ----------------
#define PADW  40
#define ROWB  (PADW * 2)         // 80 B smem row stride
#define ABUF  (128 * ROWB)       // 10240 B
#define BBUF  (128 * ROWB)       // 10240 B

__global__ __launch_bounds__(256) void gemm_mma(
    const __nv_bfloat16* __restrict__ Ag, const __nv_bfloat16* __restrict__ Bg,
    const float* __restrict__ bl, const float* __restrict__ br,
    int M, int Kp, int mBase)
{
    __shared__ alignas(128) char smem[2 * ABUF + 2 * BBUF];
    uint32_t sb = smem_u32(smem);
    int tid  = threadIdx.x;
    int wid  = tid >> 5;
    int lane = tid & 31;
    int wm   = wid >> 1;
    int wn   = wid & 1;
    int bm = mBase + blockIdx.y * 128;
    int bn = blockIdx.x * 128;

    float acc[2][8][4];
#pragma unroll
    for (int i = 0; i < 2; i++)
#pragma unroll
        for (int j = 0; j < 8; j++)
#pragma unroll
            for (int t = 0; t < 4; t++) acc[i][j][t] = 0.0f;

    int nc = Kp >> 5;

    auto load_chunk = [&](int c, int buf) {
        uint32_t sA = sb + buf * ABUF;
        uint32_t sBm = sb + 2 * ABUF + buf * BBUF;
#pragma unroll
        for (int t = tid; t < 512; t += 256) {
            int row = t >> 2, seg = t & 3;
            int grow = bm + row;
            cp_async16(sA + row * ROWB + seg * 16,
                       Ag + (size_t)grow * Kp + c * 32 + seg * 8,
                       (grow < M) ? 16 : 0);
        }
#pragma unroll
        for (int t = tid; t < 512; t += 256) {
            int row = t >> 2, seg = t & 3;
            int grow = bn + row;
            cp_async16(sBm + row * ROWB + seg * 16,
                       Bg + (size_t)grow * Kp + c * 32 + seg * 8,
                       (grow < NCAT) ? 16 : 0);
        }
    };

    load_chunk(0, 0);
    cp_commit();

    uint32_t aoff = (uint32_t)((wm * 32 + (lane & 15)) * ROWB + ((lane >> 4) * 16));
    uint32_t boff = (uint32_t)((wn * 64 + (lane & 7) + ((lane >> 4) << 3)) * ROWB
                               + (((lane >> 3) & 1) * 16));

    for (int c = 0; c < nc; c++) {
        int buf = c & 1;
        if (c + 1 < nc) { load_chunk(c + 1, buf ^ 1); cp_commit(); cp_wait<1>(); }
        else            { cp_wait<0>(); }
        __syncthreads();

        uint32_t sA = sb + buf * ABUF + aoff;
        uint32_t sBm = sb + 2 * ABUF + buf * BBUF + boff;
#pragma unroll
        for (int s = 0; s < 2; s++) {
            uint32_t a[2][4], b[4][4];
            ldm_x4(a[0], sA + s * 32);
            ldm_x4(a[1], sA + s * 32 + 16 * ROWB);
            ldm_x4(b[0], sBm + s * 32);
            ldm_x4(b[1], sBm + s * 32 + 16 * ROWB);
            ldm_x4(b[2], sBm + s * 32 + 32 * ROWB);
            ldm_x4(b[3], sBm + s * 32 + 48 * ROWB);
#pragma unroll
            for (int mt = 0; mt < 2; mt++)
#pragma unroll
                for (int nt = 0; nt < 8; nt++)
                    mma_bf16(acc[mt][nt], a[mt], &b[nt >> 1][(nt & 1) * 2]);
        }
        __syncthreads();
    }

    int r0 = lane >> 2;
    int c0 = (lane & 3) * 2;
#pragma unroll
    for (int mt = 0; mt < 2; mt++) {
#pragma unroll
        for (int nt = 0; nt < 8; nt++) {
            int col = bn + wn * 64 + nt * 8 + c0;
            if (col >= NCAT) continue;
            bool isl = (col < HCDIM);
            int cc = isl ? col : col - HCDIM;
            float* dst = isl ? g_xl : g_xr;
            const float* bias = isl ? bl : br;
            float b0 = bias[cc], b1 = bias[cc + 1];
            int row = bm + wm * 32 + mt * 16 + r0;
            if (row < M) {
                float2 v = make_float2(acc[mt][nt][0] + b0, acc[mt][nt][1] + b1);
                *(float2*)(dst + (size_t)row * HCDIM + cc) = v;
            }
            if (row + 8 < M) {
                float2 v = make_float2(acc[mt][nt][2] + b0, acc[mt][nt][3] + b1);
                *(float2*)(dst + (size_t)(row + 8) * HCDIM + cc) = v;
            }
        }
    }
}

// ---------------- CSR edge pass + fused BN statistics ----------------
// One node per 16-lane group, 2 edges/iter, group-local shuffle masks
// (0xFFFF << (tid & 16)): divergent trip counts between the warp's two groups
// make a full-warp mask UB. BN sum/sumsq fused via per-block smem reduction.
__global__ __launch_bounds__(256) void edge_csr(const float* __restrict__ att)
{
    __shared__ float satt[HCDIM];
    __shared__ float sred[256 * 20];
    for (int i = threadIdx.x; i < HCDIM; i += 256) satt[i] = att[i];
    __syncthreads();

    int gt  = blockIdx.x * 256 + threadIdx.x;
    int n   = gt >> 4;
    int sub = gt & 15;
    const unsigned gmask = 0xFFFFu << (threadIdx.x & 16);  // this 16-lane group only

    const float4* pr = (const float4*)(g_xr + (size_t)n * HCDIM);
    const float4* pw = (const float4*)satt;
    float4 xr[5], acc[5];
#pragma unroll
    for (int t = 0; t < 5; t++) {
        int i = sub + 16 * t;
        acc[t] = make_float4(0.f, 0.f, 0.f, 0.f);
        if (i < 73) xr[t] = __ldcs(pr + i);
    }
    float d0 = 0.f, d1 = 0.f, d2 = 0.f, d3 = 0.f;

    int k0 = g_off[n], k1 = g_off[n + 1];
    int k = k0;
    // ---- main loop: 2 edges per iteration ----
    for (; k + 1 < k1; k += 2) {
        int srcA = g_srcs[k];
        int srcB = g_srcs[k + 1];
        const float4* pA = (const float4*)(g_xl + (size_t)srcA * HCDIM);
        const float4* pB = (const float4*)(g_xl + (size_t)srcB * HCDIM);
        float4 a[5], b[5];
#pragma unroll
        for (int t = 0; t < 5; t++) {
            int i = sub + 16 * t;
            if (i < 73) { a[t] = pA[i]; b[t] = pB[i]; }
        }
        float u0 = 0.f, u1 = 0.f, u2 = 0.f, u3 = 0.f;
        float v0 = 0.f, v1 = 0.f, v2 = 0.f, v3 = 0.f;
#pragma unroll
        for (int t = 0; t < 5; t++) {
            int i = sub + 16 * t;
            if (i < 73) {
                float4 w = pw[i];
                int j = 4 * i;
                float f, p;
                f = a[t].x + xr[t].x; f = fmaxf(f, 0.f) + 0.2f * fminf(f, 0.f); p = f * w.x;
                if (j + 0 < 73) u0 += p; else if (j + 0 < 146) u1 += p; else if (j + 0 < 219) u2 += p; else u3 += p;
                f = a[t].y + xr[t].y; f = fmaxf(f, 0.f) + 0.2f * fminf(f, 0.f); p = f * w.y;
                if (j + 1 < 73) u0 += p; else if (j + 1 < 146) u1 += p; else if (j + 1 < 219) u2 += p; else u3 += p;
                f = a[t].z + xr[t].z; f = fmaxf(f, 0.f) + 0.2f * fminf(f, 0.f); p = f * w.z;
                if (j + 2 < 73) u0 += p; else if (j + 2 < 146) u1 += p; else if (j + 2 < 219) u2 += p; else u3 += p;
                f = a[t].w + xr[t].w; f = fmaxf(f, 0.f) + 0.2f * fminf(f, 0.f); p = f * w.w;
                if (j + 3 < 73) u0 += p; else if (j + 3 < 146) u1 += p; else if (j + 3 < 219) u2 += p; else u3 += p;

                f = b[t].x + xr[t].x; f = fmaxf(f, 0.f) + 0.2f * fminf(f, 0.f); p = f * w.x;
                if (j + 0 < 73) v0 += p; else if (j + 0 < 146) v1 += p; else if (j + 0 < 219) v2 += p; else v3 += p;
                f = b[t].y + xr[t].y; f = fmaxf(f, 0.f) + 0.2f * fminf(f, 0.f); p = f * w.y;
                if (j + 1 < 73) v0 += p; else if (j + 1 < 146) v1 += p; else if (j + 1 < 219) v2 += p; else v3 += p;
                f = b[t].z + xr[t].z; f = fmaxf(f, 0.f) + 0.2f * fminf(f, 0.f); p = f * w.z;
                if (j + 2 < 73) v0 += p; else if (j + 2 < 146) v1 += p; else if (j + 2 < 219) v2 += p; else v3 += p;
                f = b[t].w + xr[t].w; f = fmaxf(f, 0.f) + 0.2f * fminf(f, 0.f); p = f * w.w;
                if (j + 3 < 73) v0 += p; else if (j + 3 < 146) v1 += p; else if (j + 3 < 219) v2 += p; else v3 += p;
            }
        }
#pragma unroll
        for (int o = 8; o > 0; o >>= 1) {
            u0 += __shfl_xor_sync(gmask, u0, o, 16);
            v0 += __shfl_xor_sync(gmask, v0, o, 16);
            u1 += __shfl_xor_sync(gmask, u1, o, 16);
            v1 += __shfl_xor_sync(gmask, v1, o, 16);
            u2 += __shfl_xor_sync(gmask, u2, o, 16);
            v2 += __shfl_xor_sync(gmask, v2, o, 16);
            u3 += __shfl_xor_sync(gmask, u3, o, 16);
            v3 += __shfl_xor_sync(gmask, v3, o, 16);
        }
        float eA0 = expf(u0), eA1 = expf(u1), eA2 = expf(u2), eA3 = expf(u3);
        float eB0 = expf(v0), eB1 = expf(v1), eB2 = expf(v2), eB3 = expf(v3);
        d0 += eA0 + eB0; d1 += eA1 + eB1; d2 += eA2 + eB2; d3 += eA3 + eB3;
#pragma unroll
        for (int t = 0; t < 5; t++) {
            int i = sub + 16 * t;
            if (i < 73) {
                int j = 4 * i;
                float mA0 = hsel(j + 0, eA0, eA1, eA2, eA3), mB0 = hsel(j + 0, eB0, eB1, eB2, eB3);
                float mA1 = hsel(j + 1, eA0, eA1, eA2, eA3), mB1 = hsel(j + 1, eB0, eB1, eB2, eB3);
                float mA2 = hsel(j + 2, eA0, eA1, eA2, eA3), mB2 = hsel(j + 2, eB0, eB1, eB2, eB3);
                float mA3 = hsel(j + 3, eA0, eA1, eA2, eA3), mB3 = hsel(j + 3, eB0, eB1, eB2, eB3);
                acc[t].x += a[t].x * mA0 + b[t].x * mB0;
                acc[t].y += a[t].y * mA1 + b[t].y * mB1;
                acc[t].z += a[t].z * mA2 + b[t].z * mB2;
                acc[t].w += a[t].w * mA3 + b[t].w * mB3;
            }
        }
    }
    // ---- remainder: single edge ----
    for (; k < k1; k++) {
        int src = g_srcs[k];
        const float4* pl = (const float4*)(g_xl + (size_t)src * HCDIM);
        float4 a[5];
        float s0 = 0.f, s1 = 0.f, s2 = 0.f, s3 = 0.f;
#pragma unroll
        for (int t = 0; t < 5; t++) {
            int i = sub + 16 * t;
            if (i < 73) {
                float4 av = pl[i];
                a[t] = av;
                float4 w = pw[i];
                int j = 4 * i;
                float f, p;
                f = av.x + xr[t].x; f = fmaxf(f, 0.f) + 0.2f * fminf(f, 0.f); p = f * w.x;
                if (j + 0 < 73) s0 += p; else if (j + 0 < 146) s1 += p; else if (j + 0 < 219) s2 += p; else s3 += p;
                f = av.y + xr[t].y; f = fmaxf(f, 0.f) + 0.2f * fminf(f, 0.f); p = f * w.y;
                if (j + 1 < 73) s0 += p; else if (j + 1 < 146) s1 += p; else if (j + 1 < 219) s2 += p; else s3 += p;
                f = av.z + xr[t].z; f = fmaxf(f, 0.f) + 0.2f * fminf(f, 0.f); p = f * w.z;
                if (j + 2 < 73) s0 += p; else if (j + 2 < 146) s1 += p; else if (j + 2 < 219) s2 += p; else s3 += p;
                f = av.w + xr[t].w; f = fmaxf(f, 0.f) + 0.2f * fminf(f, 0.f); p = f * w.w;
                if (j + 3 < 73) s0 += p; else if (j + 3 < 146) s1 += p; else if (j + 3 < 219) s2 += p; else s3 += p;
            }
        }
#pragma unroll
        for (int o = 8; o > 0; o >>= 1) {
            s0 += __shfl_xor_sync(gmask, s0, o, 16);
            s1 += __shfl_xor_sync(gmask, s1, o, 16);
            s2 += __shfl_xor_sync(gmask, s2, o, 16);
            s3 += __shfl_xor_sync(gmask, s3, o, 16);
        }
        float e0 = expf(s0), e1 = expf(s1), e2 = expf(s2), e3 = expf(s3);
        d0 += e0; d1 += e1; d2 += e2; d3 += e3;
#pragma unroll
        for (int t = 0; t < 5; t++) {
            int i = sub + 16 * t;
            if (i < 73) {
                int j = 4 * i;
                acc[t].x += a[t].x * hsel(j + 0, e0, e1, e2, e3);
                acc[t].y += a[t].y * hsel(j + 1, e0, e1, e2, e3);
                acc[t].z += a[t].z * hsel(j + 2, e0, e1, e2, e3);
                acc[t].w += a[t].w * hsel(j + 3, e0, e1, e2, e3);
            }
        }
    }

    float i0 = 1.0f / (d0 + 1e-16f);
    float i1 = 1.0f / (d1 + 1e-16f);
    float i2 = 1.0f / (d2 + 1e-16f);
    float i3 = 1.0f / (d3 + 1e-16f);
    float4* po = (float4*)(g_agg + (size_t)n * HCDIM);
    float* myred = sred + threadIdx.x * 20;
#pragma unroll
    for (int t = 0; t < 5; t++) {
        int i = sub + 16 * t;
        if (i < 73) {
            int j = 4 * i;
            float4 o = make_float4(acc[t].x * hsel(j + 0, i0, i1, i2, i3),
                                   acc[t].y * hsel(j + 1, i0, i1, i2, i3),
                                   acc[t].z * hsel(j + 2, i0, i1, i2, i3),
                                   acc[t].w * hsel(j + 3, i0, i1, i2, i3));
            __stcs(po + i, o);
            myred[t * 4 + 0] = o.x;
            myred[t * 4 + 1] = o.y;
            myred[t * 4 + 2] = o.z;
            myred[t * 4 + 3] = o.w;
        } else {
            myred[t * 4 + 0] = 0.f;
            myred[t * 4 + 1] = 0.f;
            myred[t * 4 + 2] = 0.f;
            myred[t * 4 + 3] = 0.f;
        }
    }
    __syncthreads();

    // per-block BN partial sums over the block's 16 nodes
    for (int c = threadIdx.x; c < HCDIM; c += 256) {
        int chunk = c >> 2;
        int lanec = chunk & 15;
        int slot  = (chunk >> 4) * 4 + (c & 3);
        float s = 0.f, q = 0.f;
#pragma unroll
        for (int g = 0; g < 16; g++) {
            float v = sred[(g * 16 + lanec) * 20 + slot];
            s += v;
            q += v * v;
        }
        atomicAdd(&g_sums[c], s);
        atomicAdd(&g_sums[HCDIM + c], q);
    }
}

// ---------------- BN apply + leaky relu, fused with layer-2 A conversion (row-ranged) ----------------
__global__ __launch_bounds__(256) void bn_apply_convert(
    const float* __restrict__ X, __nv_bfloat16* __restrict__ out,
    const float* __restrict__ gamma, const float* __restrict__ beta,
    int rowBase, int nRows)
{
    size_t idx = (size_t)blockIdx.x * blockDim.x + threadIdx.x;
    size_t total = (size_t)nRows * HCDIM;
    if (idx >= total) return;
    int row = rowBase + (int)(idx / HCDIM);
    int c   = (int)(idx % HCDIM);
    const float invN = 1.0f / (float)NN;
    float mu  = g_sums[c] * invN;
    float var = g_sums[HCDIM + c] * invN - mu * mu;
    float sc  = gamma[c] * rsqrtf(var + 1e-5f);
    float v   = (X[(size_t)row * HCDIM + c] - mu) * sc + beta[c];
    v = (v > 0.0f) ? v : 0.01f * v;
    __nv_bfloat16 h = __float2bfloat16_rn(v);
    __nv_bfloat16 l = __float2bfloat16_rn(v - __bfloat162float(h));
    size_t base = (size_t)row * KP2;
    out[base + c]           = h;
    out[base + HCDIM + c]   = h;
    out[base + 2*HCDIM + c] = l;
    if (c < KP2 - 3 * HCDIM)
        out[base + 3*HCDIM + c] = __float2bfloat16_rn(0.0f);
}

// ---------------- fused BN + leaky relu + classifier (layer 2) ----------------
__global__ __launch_bounds__(256) void bn_apply_classify(
    const float* __restrict__ X,
    const float* __restrict__ gamma, const float* __restrict__ beta,
    const float* __restrict__ Wc, const float* __restrict__ bc,
    float* __restrict__ out)
{
    int gt   = blockIdx.x * 256 + threadIdx.x;
    int n    = gt >> 5;
    int lane = gt & 31;
    if (n >= NN) return;
    const float invN = 1.0f / (float)NN;
    const float* row = X + (size_t)n * HCDIM;
    float a0 = 0.f, a1 = 0.f;
    for (int c = lane; c < HCDIM; c += 32) {
        float mu  = g_sums[c] * invN;
        float var = g_sums[HCDIM + c] * invN - mu * mu;
        float sc  = gamma[c] * rsqrtf(var + 1e-5f);
        float v   = (row[c] - mu) * sc + beta[c];
        v = (v > 0.0f) ? v : 0.01f * v;
        a0 += v * Wc[c];
        a1 += v * Wc[HCDIM + c];
    }
#pragma unroll
    for (int o = 16; o > 0; o >>= 1) {
        a0 += __shfl_down_sync(0xffffffffu, a0, o);
        a1 += __shfl_down_sync(0xffffffffu, a1, o);
    }
    if (lane == 0) {
        out[(size_t)n * 2 + 0] = a0 + bc[0];
        out[(size_t)n * 2 + 1] = a1 + bc[1];
    }
}

// ---------------- launcher ----------------
extern "C" void kernel_launch(void* const* d_in, const int* in_sizes, int n_in,
                              void* d_out, int out_size)
{
    const float* x     = (const float*)d_in[0];
    const int*   ei    = (const int*)d_in[1];
    const float* Wl1   = (const float*)d_in[2];
    const float* bl1   = (const float*)d_in[3];
    const float* Wr1   = (const float*)d_in[4];
    const float* br1   = (const float*)d_in[5];
    const float* att1  = (const float*)d_in[6];
    const float* Wl2   = (const float*)d_in[8];
    const float* bl2   = (const float*)d_in[9];
    const float* Wr2   = (const float*)d_in[10];
    const float* br2   = (const float*)d_in[11];
    const float* att2  = (const float*)d_in[12];
    const float* gamma = (const float*)d_in[14];
    const float* beta  = (const float*)d_in[15];
    const float* Wc    = (const float*)d_in[16];
    const float* bc    = (const float*)d_in[17];
    float*       out   = (float*)d_out;

    float* agg; cudaGetSymbolAddress((void**)&agg, g_agg);
    __nv_bfloat16* Abig; cudaGetSymbolAddress((void**)&Abig, g_Abig);
    __nv_bfloat16* Bcat; cudaGetSymbolAddress((void**)&Bcat, g_Bcat);
    __nv_bfloat16* B1 = Bcat;
    __nv_bfloat16* B2 = Bcat + (size_t)NCAT * KP2;

    static cudaStream_t s2s = nullptr;
    static cudaEvent_t evFork = nullptr, evJoin = nullptr, evC = nullptr, evG = nullptr;
    if (!s2s) {
        cudaStreamCreateWithFlags(&s2s, cudaStreamNonBlocking);
        cudaEventCreateWithFlags(&evFork, cudaEventDisableTiming);
        cudaEventCreateWithFlags(&evJoin, cudaEventDisableTiming);
        cudaEventCreateWithFlags(&evC, cudaEventDisableTiming);
        cudaEventCreateWithFlags(&evG, cudaEventDisableTiming);
    }

    dim3 gemm_grid1((NCAT + 127) / 128, (NN + 127) / 128);          // (5, 391)
    dim3 gemm_grid2a((NCAT + 127) / 128, HALFR / 128);              // (5, 196)
    dim3 gemm_grid2b((NCAT + 127) / 128, (NN - HALFR + 127) / 128); // (5, 195)
    int e_blocks    = (EE + 255) / 256;
    int edge_blocks = (NN * 16 + 255) / 256;                 // 3125 exact
    int cls_blocks  = (NN * 32 + 255) / 256;
    int convA1_blocks = (int)(((size_t)NN * KP1 + 255) / 256);
    int convB1_blocks = (HCDIM * KP1 + 255) / 256;
    int convB2_blocks = (HCDIM * KP2 + 255) / 256;
    int bnc0_blocks = (int)(((size_t)HALFR * HCDIM + 255) / 256);
    int bnc1_blocks = (int)(((size_t)(NN - HALFR) * HCDIM + 255) / 256);

    // ---- fork: chain B (CSR build + layer-2 weight conversions) on s2s ----
    cudaEventRecord(evFork, 0);
    cudaStreamWaitEvent(s2s, evFork, 0);
    zero_deg_sums<<<(NN + 255) / 256, 256, 0, s2s>>>();
    csr_count   <<<e_blocks, 256, 0, s2s>>>(ei);
    csr_scan    <<<1, 1024, 0, s2s>>>();
    csr_scatter <<<e_blocks, 256, 0, s2s>>>(ei);
    convert_split3<<<convB2_blocks, 256, 0, s2s>>>(Wl2, B2,                     HCDIM, HCDIM, KP2, 1);
    convert_split3<<<convB2_blocks, 256, 0, s2s>>>(Wr2, B2 + (size_t)HCDIM*KP2, HCDIM, HCDIM, KP2, 1);
    cudaEventRecord(evJoin, s2s);

    // ---- chain A: layer-1 GEMM inputs + GEMM (default stream) ----
    convert_split3<<<convB1_blocks, 256>>>(Wl1, B1,                     HCDIM, FIN, KP1, 1);
    convert_split3<<<convB1_blocks, 256>>>(Wr1, B1 + (size_t)HCDIM*KP1, HCDIM, FIN, KP1, 1);
    convert_split3<<<convA1_blocks, 256>>>(x,   Abig, NN, FIN, KP1, 0);
    gemm_mma<<<gemm_grid1, 256>>>(Abig, B1, bl1, br1, NN, KP1, 0);

    // ---- join: edge_csr needs gemm1 + CSR + zeroed sums ----
    cudaStreamWaitEvent(0, evJoin, 0);

    // ---------- layer 1 (BN stats fused into edge_csr) ----------
    edge_csr<<<edge_blocks, 256>>>(att1);

    // ---- pipelined bn_convert / gemm2: half0 converts, gemm2a (s2s) starts on it
    //      while half1 converts; gemm2b on stream0; edge2 joins both. ----
    bn_apply_convert<<<bnc0_blocks, 256>>>(agg, Abig, gamma, beta, 0, HALFR);
    cudaEventRecord(evC, 0);
    bn_apply_convert<<<bnc1_blocks, 256>>>(agg, Abig, gamma, beta, HALFR, NN - HALFR);
    zero_sums<<<3, 256>>>();
    cudaStreamWaitEvent(s2s, evC, 0);
    gemm_mma<<<gemm_grid2a, 256, 0, s2s>>>(Abig, B2, bl2, br2, NN, KP2, 0);
    cudaEventRecord(evG, s2s);
    gemm_mma<<<gemm_grid2b, 256>>>(Abig, B2, bl2, br2, NN, KP2, HALFR);
    cudaStreamWaitEvent(0, evG, 0);

    // ---------- layer 2 ----------
    edge_csr<<<edge_blocks, 256>>>(att2);
    bn_apply_classify<<<cls_blocks, 256>>>(agg, gamma, beta, Wc, bc, out);

    (void)in_sizes; (void)n_in; (void)out_size;
}